// round 1
// baseline (speedup 1.0000x reference)
#include <cuda_runtime.h>

#define N_TOK 8192
#define DMODEL 1024
#define NEXP 8
#define RANK 16
#define HCOLS (NEXP * RANK)     // 128
#define KAUG (DMODEL + HCOLS)   // 1152

// Scratch (device globals — no allocation allowed)
__device__ float g_combine[N_TOK * NEXP];        // dense combine weights [N, E]
__device__ float g_hw[N_TOK * HCOLS];            // scaled LoRA hidden [N, 128]
__device__ float g_Baug[KAUG * DMODEL];          // [W_base^T ; B_flat] k-major [1152, 1024]

// ---------------------------------------------------------------------------
// Kernel 0a: transpose W_base into g_Baug rows [0, 1024): Baug[d][j] = W[j][d]
// ---------------------------------------------------------------------------
__global__ void transpose_w(const float* __restrict__ W) {
    __shared__ float tile[32][33];
    int jx = blockIdx.x * 32 + threadIdx.x;   // d-dim of W row (contiguous)
    int ry = blockIdx.y * 32 + threadIdx.y;   // j-dim of W (row index)
    tile[threadIdx.y][threadIdx.x] = W[ry * DMODEL + jx];
    __syncthreads();
    int od = blockIdx.x * 32 + threadIdx.y;   // output row (= d)
    int oj = blockIdx.y * 32 + threadIdx.x;   // output col (= j)
    g_Baug[od * DMODEL + oj] = tile[threadIdx.x][threadIdx.y];
}

// ---------------------------------------------------------------------------
// Kernel 0b: copy B [E,R,D] = [128,1024] (already k-major) under the transpose
// ---------------------------------------------------------------------------
__global__ void copy_b(const float* __restrict__ B) {
    int r = blockIdx.x;               // 0..127
    int j4 = threadIdx.x * 4;         // 256 threads * 4 = 1024
    *(float4*)(g_Baug + (DMODEL + r) * DMODEL + j4) =
        *(const float4*)(B + r * DMODEL + j4);
}

// ---------------------------------------------------------------------------
// Kernel 1: gating. One warp per token: 8 logits, top-2, softmax -> g_combine.
// ---------------------------------------------------------------------------
__global__ __launch_bounds__(256) void gating_kernel(const float* __restrict__ x,
                                                     const float* __restrict__ Wg) {
    int warp = threadIdx.x >> 5, lane = threadIdx.x & 31;
    int t = blockIdx.x * 8 + warp;
    const float* xr = x + (size_t)t * DMODEL;
    float acc[NEXP];
#pragma unroll
    for (int e = 0; e < NEXP; e++) acc[e] = 0.f;
    for (int d = lane; d < DMODEL; d += 32) {
        float xv = xr[d];
#pragma unroll
        for (int e = 0; e < NEXP; e++) acc[e] += xv * Wg[e * DMODEL + d];
    }
#pragma unroll
    for (int e = 0; e < NEXP; e++) {
#pragma unroll
        for (int o = 16; o > 0; o >>= 1)
            acc[e] += __shfl_xor_sync(0xffffffffu, acc[e], o);
    }
    if (lane == 0) {
        int i0 = 0; float v0 = acc[0];
#pragma unroll
        for (int e = 1; e < NEXP; e++)
            if (acc[e] > v0) { v0 = acc[e]; i0 = e; }
        int i1 = -1; float v1 = -3.4e38f;
#pragma unroll
        for (int e = 0; e < NEXP; e++)
            if (e != i0 && acc[e] > v1) { v1 = acc[e]; i1 = e; }
        float e1 = expf(v1 - v0);
        float w0 = 1.f / (1.f + e1);
        float w1 = e1 * w0;
        float* c = g_combine + t * NEXP;
#pragma unroll
        for (int e = 0; e < NEXP; e++) c[e] = 0.f;
        c[i0] = w0;
        c[i1] = w1;
    }
}

// ---------------------------------------------------------------------------
// Kernel 2: h GEMM [8192,1024] @ A_resh[1024,128], epilogue scales by combine.
// 64x64 tile, BK=16, 256 threads, 4x4 per thread.
// ---------------------------------------------------------------------------
__global__ __launch_bounds__(256) void h_kernel(const float* __restrict__ x,
                                                const float* __restrict__ A) {
    const int n0 = blockIdx.x * 64;
    const int m0 = blockIdx.y * 64;
    __shared__ float As[16][64];
    __shared__ float Bs[16][64];
    int tid = threadIdx.x;
    int ty = tid >> 4, tx = tid & 15;
    float accv[4][4];
#pragma unroll
    for (int i = 0; i < 4; i++)
#pragma unroll
        for (int j = 0; j < 4; j++) accv[i][j] = 0.f;

    int arow = tid >> 2;            // 0..63
    int akg  = (tid & 3) * 4;       // 0,4,8,12
    int bk   = tid >> 4;            // 0..15
    int bj   = (tid & 15) * 4;      // 0..60

    const float* xrow = x + (size_t)(m0 + arow) * DMODEL;
    int colb = n0 + bj;
    int e = colb >> 4;
    int r = colb & 15;
    const float* Abase = A + (size_t)e * DMODEL * RANK + r;

    for (int k0 = 0; k0 < DMODEL; k0 += 16) {
        float4 av = *(const float4*)(xrow + k0 + akg);
        As[akg + 0][arow] = av.x;
        As[akg + 1][arow] = av.y;
        As[akg + 2][arow] = av.z;
        As[akg + 3][arow] = av.w;
        float4 bv = *(const float4*)(Abase + (size_t)(k0 + bk) * RANK);
        *(float4*)&Bs[bk][bj] = bv;
        __syncthreads();
#pragma unroll
        for (int k = 0; k < 16; k++) {
            float a[4], b[4];
            *(float4*)a = *(float4*)&As[k][ty * 4];
            *(float4*)b = *(float4*)&Bs[k][tx * 4];
#pragma unroll
            for (int i = 0; i < 4; i++)
#pragma unroll
                for (int j = 0; j < 4; j++) accv[i][j] += a[i] * b[j];
        }
        __syncthreads();
    }
#pragma unroll
    for (int i = 0; i < 4; i++) {
        int row = m0 + ty * 4 + i;
#pragma unroll
        for (int j = 0; j < 4; j++) {
            int col = n0 + tx * 4 + j;
            g_hw[(size_t)row * HCOLS + col] =
                accv[i][j] * g_combine[row * NEXP + (col >> 4)];
        }
    }
}

// ---------------------------------------------------------------------------
// Kernel 3: fused big GEMM  out = [x | hw] @ g_Baug + bias
// 128x128 tile, BK=8, 256 threads, 8x8 per thread.
// ---------------------------------------------------------------------------
__global__ __launch_bounds__(256) void big_gemm(const float* __restrict__ x,
                                                const float* __restrict__ bias,
                                                float* __restrict__ out) {
    const int n0 = blockIdx.x * 128;
    const int m0 = blockIdx.y * 128;
    __shared__ float As[8][128];
    __shared__ float Bs[8][128];
    int tid = threadIdx.x;
    int ty = tid >> 4, tx = tid & 15;
    float acc[8][8];
#pragma unroll
    for (int i = 0; i < 8; i++)
#pragma unroll
        for (int j = 0; j < 8; j++) acc[i][j] = 0.f;

    int arow = tid >> 1;            // 0..127
    int akg  = (tid & 1) * 4;       // 0 or 4
    int bk   = tid >> 5;            // 0..7
    int bj   = (tid & 31) * 4;      // 0..124

    const float* xrow = x + (size_t)(m0 + arow) * DMODEL;
    const float* hrow = g_hw + (size_t)(m0 + arow) * HCOLS;

    for (int k0 = 0; k0 < KAUG; k0 += 8) {
        float4 av;
        if (k0 < DMODEL) av = *(const float4*)(xrow + k0 + akg);
        else             av = *(const float4*)(hrow + (k0 - DMODEL) + akg);
        As[akg + 0][arow] = av.x;
        As[akg + 1][arow] = av.y;
        As[akg + 2][arow] = av.z;
        As[akg + 3][arow] = av.w;
        float4 bv = *(const float4*)(g_Baug + (size_t)(k0 + bk) * DMODEL + n0 + bj);
        *(float4*)&Bs[bk][bj] = bv;
        __syncthreads();
#pragma unroll
        for (int k = 0; k < 8; k++) {
            float a[8], b[8];
            *(float4*)&a[0] = *(float4*)&As[k][ty * 8];
            *(float4*)&a[4] = *(float4*)&As[k][ty * 8 + 4];
            *(float4*)&b[0] = *(float4*)&Bs[k][tx * 8];
            *(float4*)&b[4] = *(float4*)&Bs[k][tx * 8 + 4];
#pragma unroll
            for (int i = 0; i < 8; i++)
#pragma unroll
                for (int j = 0; j < 8; j++) acc[i][j] += a[i] * b[j];
        }
        __syncthreads();
    }

    int col = n0 + tx * 8;
    float bcol[8];
#pragma unroll
    for (int j = 0; j < 8; j++) bcol[j] = bias[col + j];
#pragma unroll
    for (int i = 0; i < 8; i++) {
        int row = m0 + ty * 8 + i;
        float4 o0, o1;
        o0.x = acc[i][0] + bcol[0];
        o0.y = acc[i][1] + bcol[1];
        o0.z = acc[i][2] + bcol[2];
        o0.w = acc[i][3] + bcol[3];
        o1.x = acc[i][4] + bcol[4];
        o1.y = acc[i][5] + bcol[5];
        o1.z = acc[i][6] + bcol[6];
        o1.w = acc[i][7] + bcol[7];
        *(float4*)(out + (size_t)row * DMODEL + col) = o0;
        *(float4*)(out + (size_t)row * DMODEL + col + 4) = o1;
    }
}

// ---------------------------------------------------------------------------
extern "C" void kernel_launch(void* const* d_in, const int* in_sizes, int n_in,
                              void* d_out, int out_size) {
    const float* x  = (const float*)d_in[0];
    const float* Wg = (const float*)d_in[1];
    const float* A  = (const float*)d_in[2];
    const float* B  = (const float*)d_in[3];
    const float* Wb = (const float*)d_in[4];
    const float* bb = (const float*)d_in[5];
    float* out = (float*)d_out;

    transpose_w<<<dim3(32, 32), dim3(32, 32)>>>(Wb);
    copy_b<<<128, 256>>>(B);
    gating_kernel<<<N_TOK / 8, 256>>>(x, Wg);
    h_kernel<<<dim3(2, 128), 256>>>(x, A);
    big_gemm<<<dim3(8, 64), 256>>>(x, bb, out);
}

// round 2
// speedup vs baseline: 2.1218x; 2.1218x over previous
#include <cuda_runtime.h>

#define N_TOK 8192
#define DMODEL 1024
#define NEXP 8
#define RANK 16
#define HCOLS (NEXP * RANK)     // 128
#define KAUG (DMODEL + HCOLS)   // 1152

// Scratch (device globals — no allocation allowed)
__device__ float g_combine[N_TOK * NEXP];        // dense combine weights [N, E]
__device__ float g_hw[N_TOK * HCOLS];            // scaled LoRA hidden [N, 128]
__device__ float g_Baug[KAUG * DMODEL];          // [W_base^T ; B_flat] k-major [1152, 1024]

// ---------------------------------------------------------------------------
// tf32 helpers
// ---------------------------------------------------------------------------
__device__ __forceinline__ unsigned f2tf(float f) {
    unsigned u;
    asm("cvt.rna.tf32.f32 %0, %1;" : "=r"(u) : "f"(f));
    return u;
}

__device__ __forceinline__ void mma_tf32(float* c, const unsigned* a, const unsigned* b) {
    asm volatile(
        "mma.sync.aligned.m16n8k8.row.col.f32.tf32.tf32.f32 "
        "{%0,%1,%2,%3}, {%4,%5,%6,%7}, {%8,%9}, {%0,%1,%2,%3};"
        : "+f"(c[0]), "+f"(c[1]), "+f"(c[2]), "+f"(c[3])
        : "r"(a[0]), "r"(a[1]), "r"(a[2]), "r"(a[3]), "r"(b[0]), "r"(b[1]));
}

// ---------------------------------------------------------------------------
// Kernel 0a: transpose W_base into g_Baug rows [0, 1024): Baug[d][j] = W[j][d]
// ---------------------------------------------------------------------------
__global__ void transpose_w(const float* __restrict__ W) {
    __shared__ float tile[32][33];
    int jx = blockIdx.x * 32 + threadIdx.x;
    int ry = blockIdx.y * 32 + threadIdx.y;
    tile[threadIdx.y][threadIdx.x] = W[ry * DMODEL + jx];
    __syncthreads();
    int od = blockIdx.x * 32 + threadIdx.y;
    int oj = blockIdx.y * 32 + threadIdx.x;
    g_Baug[od * DMODEL + oj] = tile[threadIdx.x][threadIdx.y];
}

// ---------------------------------------------------------------------------
// Kernel 0b: copy B [E,R,D] = [128,1024] (already k-major) under the transpose
// ---------------------------------------------------------------------------
__global__ void copy_b(const float* __restrict__ B) {
    int r = blockIdx.x;
    int j4 = threadIdx.x * 4;
    *(float4*)(g_Baug + (DMODEL + r) * DMODEL + j4) =
        *(const float4*)(B + r * DMODEL + j4);
}

// ---------------------------------------------------------------------------
// Kernel 1: gating (exact fp32). One warp per token.
// ---------------------------------------------------------------------------
__global__ __launch_bounds__(256) void gating_kernel(const float* __restrict__ x,
                                                     const float* __restrict__ Wg) {
    int warp = threadIdx.x >> 5, lane = threadIdx.x & 31;
    int t = blockIdx.x * 8 + warp;
    const float* xr = x + (size_t)t * DMODEL;
    float acc[NEXP];
#pragma unroll
    for (int e = 0; e < NEXP; e++) acc[e] = 0.f;
    for (int d = lane; d < DMODEL; d += 32) {
        float xv = xr[d];
#pragma unroll
        for (int e = 0; e < NEXP; e++) acc[e] += xv * Wg[e * DMODEL + d];
    }
#pragma unroll
    for (int e = 0; e < NEXP; e++) {
#pragma unroll
        for (int o = 16; o > 0; o >>= 1)
            acc[e] += __shfl_xor_sync(0xffffffffu, acc[e], o);
    }
    if (lane == 0) {
        int i0 = 0; float v0 = acc[0];
#pragma unroll
        for (int e = 1; e < NEXP; e++)
            if (acc[e] > v0) { v0 = acc[e]; i0 = e; }
        int i1 = -1; float v1 = -3.4e38f;
#pragma unroll
        for (int e = 0; e < NEXP; e++)
            if (e != i0 && acc[e] > v1) { v1 = acc[e]; i1 = e; }
        float e1 = expf(v1 - v0);
        float w0 = 1.f / (1.f + e1);
        float w1 = e1 * w0;
        float* c = g_combine + t * NEXP;
#pragma unroll
        for (int e = 0; e < NEXP; e++) c[e] = 0.f;
        c[i0] = w0;
        c[i1] = w1;
    }
}

// ---------------------------------------------------------------------------
// Kernel 2: h GEMM via tf32 mma: g_hw = (x @ A_resh) * combine
// Block 64x128, BK=16, 256 threads; warps 2(M)x4(N), warp tile 32x32.
// ---------------------------------------------------------------------------
__global__ __launch_bounds__(256, 2) void h_kernel(const float* __restrict__ x,
                                                   const float* __restrict__ A) {
    __shared__ unsigned As[64][20];    // A row-major [m][k], pad to 20
    __shared__ unsigned Bs[16][136];   // B k-major  [k][n], pad to 136
    const int tid = threadIdx.x;
    const int lane = tid & 31, warp = tid >> 5;
    const int grp = lane >> 2, thr = lane & 3;
    const int wm0 = (warp & 1) * 32;
    const int wn0 = (warp >> 1) * 32;
    const int m0 = blockIdx.x * 64;

    float acc[2][4][4];
#pragma unroll
    for (int i = 0; i < 2; i++)
#pragma unroll
        for (int j = 0; j < 4; j++)
#pragma unroll
            for (int q = 0; q < 4; q++) acc[i][j][q] = 0.f;

    const int arow = tid >> 2, akh = (tid & 3) * 4;   // 64 rows x 16 k
    const int bkr = tid >> 4, bnc = (tid & 15) * 8;   // 16 k x 128 n
    const int be = bnc >> 4, br = bnc & 15;
    const float* xrow = x + (size_t)(m0 + arow) * DMODEL;
    const float* Abase = A + (size_t)be * DMODEL * RANK + br;

    float4 av = *(const float4*)(xrow + akh);
    float4 bv0 = *(const float4*)(Abase + (size_t)bkr * RANK);
    float4 bv1 = *(const float4*)(Abase + (size_t)bkr * RANK + 4);

    for (int k0 = 0; k0 < DMODEL; k0 += 16) {
        As[arow][akh + 0] = f2tf(av.x);
        As[arow][akh + 1] = f2tf(av.y);
        As[arow][akh + 2] = f2tf(av.z);
        As[arow][akh + 3] = f2tf(av.w);
        Bs[bkr][bnc + 0] = f2tf(bv0.x);
        Bs[bkr][bnc + 1] = f2tf(bv0.y);
        Bs[bkr][bnc + 2] = f2tf(bv0.z);
        Bs[bkr][bnc + 3] = f2tf(bv0.w);
        Bs[bkr][bnc + 4] = f2tf(bv1.x);
        Bs[bkr][bnc + 5] = f2tf(bv1.y);
        Bs[bkr][bnc + 6] = f2tf(bv1.z);
        Bs[bkr][bnc + 7] = f2tf(bv1.w);
        __syncthreads();
        int kn = k0 + 16;
        if (kn < DMODEL) {
            av = *(const float4*)(xrow + kn + akh);
            bv0 = *(const float4*)(Abase + (size_t)(kn + bkr) * RANK);
            bv1 = *(const float4*)(Abase + (size_t)(kn + bkr) * RANK + 4);
        }
#pragma unroll
        for (int ks = 0; ks < 16; ks += 8) {
            unsigned a[2][4];
#pragma unroll
            for (int i = 0; i < 2; i++) {
                int r = wm0 + i * 16;
                a[i][0] = As[r + grp][ks + thr];
                a[i][1] = As[r + 8 + grp][ks + thr];
                a[i][2] = As[r + grp][ks + thr + 4];
                a[i][3] = As[r + 8 + grp][ks + thr + 4];
            }
            unsigned b[4][2];
#pragma unroll
            for (int j = 0; j < 4; j++) {
                b[j][0] = Bs[ks + thr][wn0 + j * 8 + grp];
                b[j][1] = Bs[ks + thr + 4][wn0 + j * 8 + grp];
            }
#pragma unroll
            for (int i = 0; i < 2; i++)
#pragma unroll
                for (int j = 0; j < 4; j++)
                    mma_tf32(acc[i][j], a[i], b[j]);
        }
        __syncthreads();
    }

#pragma unroll
    for (int i = 0; i < 2; i++) {
        int r0 = m0 + wm0 + i * 16 + grp;
        const float* cw0 = g_combine + r0 * NEXP;
        const float* cw1 = g_combine + (r0 + 8) * NEXP;
#pragma unroll
        for (int j = 0; j < 4; j++) {
            int c = wn0 + j * 8 + 2 * thr;
            int e = (wn0 + j * 8) >> 4;
            float w0 = cw0[e], w1 = cw1[e];
            g_hw[(size_t)r0 * HCOLS + c]       = acc[i][j][0] * w0;
            g_hw[(size_t)r0 * HCOLS + c + 1]   = acc[i][j][1] * w0;
            g_hw[(size_t)(r0 + 8) * HCOLS + c]     = acc[i][j][2] * w1;
            g_hw[(size_t)(r0 + 8) * HCOLS + c + 1] = acc[i][j][3] * w1;
        }
    }
}

// ---------------------------------------------------------------------------
// Kernel 3: big GEMM via tf32 mma: out = [x | hw] @ g_Baug + bias
// Block 128x128, BK=16, 256 threads; warps 4(M)x2(N), warp tile 32x64.
// ---------------------------------------------------------------------------
__global__ __launch_bounds__(256, 2) void big_gemm(const float* __restrict__ x,
                                                   const float* __restrict__ bias,
                                                   float* __restrict__ out) {
    __shared__ unsigned As[128][20];   // A row-major [m][k]
    __shared__ unsigned Bs[16][136];   // B k-major  [k][n]
    const int tid = threadIdx.x;
    const int lane = tid & 31, warp = tid >> 5;
    const int grp = lane >> 2, thr = lane & 3;
    const int wm0 = (warp & 3) * 32;
    const int wn0 = (warp >> 2) * 64;
    const int m0 = blockIdx.y * 128, n0 = blockIdx.x * 128;

    float acc[2][8][4];
#pragma unroll
    for (int i = 0; i < 2; i++)
#pragma unroll
        for (int j = 0; j < 8; j++)
#pragma unroll
            for (int q = 0; q < 4; q++) acc[i][j][q] = 0.f;

    const int arow = tid >> 1, akh = (tid & 1) * 8;   // 128 rows x 16 k
    const int bkr = tid >> 4, bnc = (tid & 15) * 8;   // 16 k x 128 n
    const float* xrow = x + (size_t)(m0 + arow) * DMODEL;
    const float* hrow = g_hw + (size_t)(m0 + arow) * HCOLS;

    float4 av0 = *(const float4*)(xrow + akh);
    float4 av1 = *(const float4*)(xrow + akh + 4);
    float4 bv0 = *(const float4*)(g_Baug + (size_t)bkr * DMODEL + n0 + bnc);
    float4 bv1 = *(const float4*)(g_Baug + (size_t)bkr * DMODEL + n0 + bnc + 4);

    for (int k0 = 0; k0 < KAUG; k0 += 16) {
        As[arow][akh + 0] = f2tf(av0.x);
        As[arow][akh + 1] = f2tf(av0.y);
        As[arow][akh + 2] = f2tf(av0.z);
        As[arow][akh + 3] = f2tf(av0.w);
        As[arow][akh + 4] = f2tf(av1.x);
        As[arow][akh + 5] = f2tf(av1.y);
        As[arow][akh + 6] = f2tf(av1.z);
        As[arow][akh + 7] = f2tf(av1.w);
        Bs[bkr][bnc + 0] = f2tf(bv0.x);
        Bs[bkr][bnc + 1] = f2tf(bv0.y);
        Bs[bkr][bnc + 2] = f2tf(bv0.z);
        Bs[bkr][bnc + 3] = f2tf(bv0.w);
        Bs[bkr][bnc + 4] = f2tf(bv1.x);
        Bs[bkr][bnc + 5] = f2tf(bv1.y);
        Bs[bkr][bnc + 6] = f2tf(bv1.z);
        Bs[bkr][bnc + 7] = f2tf(bv1.w);
        __syncthreads();
        int kn = k0 + 16;
        if (kn < KAUG) {
            if (kn < DMODEL) {
                av0 = *(const float4*)(xrow + kn + akh);
                av1 = *(const float4*)(xrow + kn + akh + 4);
            } else {
                av0 = *(const float4*)(hrow + (kn - DMODEL) + akh);
                av1 = *(const float4*)(hrow + (kn - DMODEL) + akh + 4);
            }
            bv0 = *(const float4*)(g_Baug + (size_t)(kn + bkr) * DMODEL + n0 + bnc);
            bv1 = *(const float4*)(g_Baug + (size_t)(kn + bkr) * DMODEL + n0 + bnc + 4);
        }
#pragma unroll
        for (int ks = 0; ks < 16; ks += 8) {
            unsigned a[2][4];
#pragma unroll
            for (int i = 0; i < 2; i++) {
                int r = wm0 + i * 16;
                a[i][0] = As[r + grp][ks + thr];
                a[i][1] = As[r + 8 + grp][ks + thr];
                a[i][2] = As[r + grp][ks + thr + 4];
                a[i][3] = As[r + 8 + grp][ks + thr + 4];
            }
            unsigned b[8][2];
#pragma unroll
            for (int j = 0; j < 8; j++) {
                b[j][0] = Bs[ks + thr][wn0 + j * 8 + grp];
                b[j][1] = Bs[ks + thr + 4][wn0 + j * 8 + grp];
            }
#pragma unroll
            for (int i = 0; i < 2; i++)
#pragma unroll
                for (int j = 0; j < 8; j++)
                    mma_tf32(acc[i][j], a[i], b[j]);
        }
        __syncthreads();
    }

#pragma unroll
    for (int i = 0; i < 2; i++) {
        int r0 = m0 + wm0 + i * 16 + grp;
#pragma unroll
        for (int j = 0; j < 8; j++) {
            int c = n0 + wn0 + j * 8 + 2 * thr;
            float b0v = bias[c], b1v = bias[c + 1];
            float2 o0 = make_float2(acc[i][j][0] + b0v, acc[i][j][1] + b1v);
            float2 o1 = make_float2(acc[i][j][2] + b0v, acc[i][j][3] + b1v);
            *(float2*)(out + (size_t)r0 * DMODEL + c) = o0;
            *(float2*)(out + (size_t)(r0 + 8) * DMODEL + c) = o1;
        }
    }
}

// ---------------------------------------------------------------------------
extern "C" void kernel_launch(void* const* d_in, const int* in_sizes, int n_in,
                              void* d_out, int out_size) {
    const float* x  = (const float*)d_in[0];
    const float* Wg = (const float*)d_in[1];
    const float* A  = (const float*)d_in[2];
    const float* B  = (const float*)d_in[3];
    const float* Wb = (const float*)d_in[4];
    const float* bb = (const float*)d_in[5];
    float* out = (float*)d_out;

    transpose_w<<<dim3(32, 32), dim3(32, 32)>>>(Wb);
    copy_b<<<128, 256>>>(B);
    gating_kernel<<<N_TOK / 8, 256>>>(x, Wg);
    h_kernel<<<128, 256>>>(x, A);
    big_gemm<<<dim3(8, 64), 256>>>(x, bb, out);
}

// round 4
// speedup vs baseline: 3.7851x; 1.7839x over previous
#include <cuda_runtime.h>
#include <cstdint>

#define N_TOK 8192
#define DMODEL 1024
#define NEXP 8
#define RANK 16
#define HCOLS 128
#define KAUG 1152            // 1024 + 128

// ---------------------------------------------------------------------------
// Device scratch (no allocation allowed)
// ---------------------------------------------------------------------------
__device__ float g_combine[N_TOK * NEXP];                  // [N, 8]
__device__ float g_xaug[(size_t)N_TOK * KAUG];             // tf32 [x | hw], row-major [m][k]
__device__ float g_Bt[(size_t)DMODEL * KAUG];              // tf32 [n][k] = [Wb row | B^T row]
__device__ float g_At[HCOLS * DMODEL];                     // tf32 [n=e*16+r][k]

// ---------------------------------------------------------------------------
// Helpers
// ---------------------------------------------------------------------------
__device__ __forceinline__ float f2tf(float f) {
    unsigned u; asm("cvt.rna.tf32.f32 %0, %1;" : "=r"(u) : "f"(f));
    return __uint_as_float(u);
}
__device__ __forceinline__ uint32_t smem_u32(const void* p) {
    uint32_t a;
    asm("{ .reg .u64 t; cvta.to.shared.u64 t, %1; cvt.u32.u64 %0, t; }" : "=r"(a) : "l"(p));
    return a;
}
__device__ __forceinline__ void ldsm4(uint32_t* r, uint32_t addr) {
    asm volatile("ldmatrix.sync.aligned.m8n8.x4.shared.b16 {%0,%1,%2,%3}, [%4];"
                 : "=r"(r[0]), "=r"(r[1]), "=r"(r[2]), "=r"(r[3]) : "r"(addr));
}
__device__ __forceinline__ void cp16(uint32_t dst, const void* src) {
    asm volatile("cp.async.cg.shared.global [%0], [%1], 16;" :: "r"(dst), "l"(src));
}
__device__ __forceinline__ void cp_commit() {
    asm volatile("cp.async.commit_group;" ::: "memory");
}
template <int N> __device__ __forceinline__ void cp_wait() {
    asm volatile("cp.async.wait_group %0;" :: "n"(N) : "memory");
}
__device__ __forceinline__ void mma_tf32(float* c, const uint32_t* a, const uint32_t* b) {
    asm volatile(
        "mma.sync.aligned.m16n8k8.row.col.f32.tf32.tf32.f32 "
        "{%0,%1,%2,%3}, {%4,%5,%6,%7}, {%8,%9}, {%0,%1,%2,%3};"
        : "+f"(c[0]), "+f"(c[1]), "+f"(c[2]), "+f"(c[3])
        : "r"(a[0]), "r"(a[1]), "r"(a[2]), "r"(a[3]), "r"(b[0]), "r"(b[1]));
}

// ---------------------------------------------------------------------------
// Prep 1: g_Bt rows, cols [0,1024) = tf32(W_base[n][k])  (W_base is [N,K] k-major)
// ---------------------------------------------------------------------------
__global__ void build_bt_base(const float* __restrict__ Wb) {
    int n = blockIdx.x;
    int j = threadIdx.x * 4;
    float4 v = *(const float4*)(Wb + (size_t)n * DMODEL + j);
    float4 o = make_float4(f2tf(v.x), f2tf(v.y), f2tf(v.z), f2tf(v.w));
    *(float4*)(g_Bt + (size_t)n * KAUG + j) = o;
}

// Prep 2: g_Bt[n][1024+i] = tf32(B[i][n])  (B flattens to [128][1024])
__global__ void build_bt_lora(const float* __restrict__ B) {
    __shared__ float tile[32][33];
    int n0 = blockIdx.x * 32, i0 = blockIdx.y * 32;
    tile[threadIdx.y][threadIdx.x] =
        f2tf(B[(size_t)(i0 + threadIdx.y) * DMODEL + n0 + threadIdx.x]);
    __syncthreads();
    g_Bt[(size_t)(n0 + threadIdx.y) * KAUG + DMODEL + i0 + threadIdx.x] =
        tile[threadIdx.x][threadIdx.y];
}

// Prep 3: g_At[e*16+r][k] = tf32(A[e][k][r])
__global__ void build_at(const float* __restrict__ A) {
    __shared__ float tile[16][17];
    int e = blockIdx.y, k0 = blockIdx.x * 16;
    tile[threadIdx.x][threadIdx.y] =
        f2tf(A[(size_t)e * DMODEL * RANK + (size_t)(k0 + threadIdx.y) * RANK + threadIdx.x]);
    __syncthreads();
    g_At[(size_t)(e * RANK + threadIdx.y) * DMODEL + k0 + threadIdx.x] =
        tile[threadIdx.y][threadIdx.x];
}

// ---------------------------------------------------------------------------
// Gating + fused x->tf32 conversion into g_xaug[:, 0:1024]. One warp/token.
// ---------------------------------------------------------------------------
__global__ __launch_bounds__(256) void gating_cvt(const float* __restrict__ x,
                                                  const float* __restrict__ Wg) {
    int warp = threadIdx.x >> 5, lane = threadIdx.x & 31;
    int t = blockIdx.x * 8 + warp;
    const float* xr = x + (size_t)t * DMODEL;
    float* xo = g_xaug + (size_t)t * KAUG;
    float acc[NEXP];
#pragma unroll
    for (int e = 0; e < NEXP; e++) acc[e] = 0.f;
#pragma unroll
    for (int kk = 0; kk < 8; kk++) {
        int col = kk * 128 + lane * 4;
        float4 v = *(const float4*)(xr + col);
        float4 cv = make_float4(f2tf(v.x), f2tf(v.y), f2tf(v.z), f2tf(v.w));
        *(float4*)(xo + col) = cv;
#pragma unroll
        for (int e = 0; e < NEXP; e++) {
            float4 w = *(const float4*)(Wg + e * DMODEL + col);
            acc[e] += v.x * w.x + v.y * w.y + v.z * w.z + v.w * w.w;
        }
    }
#pragma unroll
    for (int e = 0; e < NEXP; e++) {
#pragma unroll
        for (int o = 16; o > 0; o >>= 1)
            acc[e] += __shfl_xor_sync(0xffffffffu, acc[e], o);
    }
    if (lane == 0) {
        int i0 = 0; float v0 = acc[0];
#pragma unroll
        for (int e = 1; e < NEXP; e++)
            if (acc[e] > v0) { v0 = acc[e]; i0 = e; }
        int i1 = -1; float v1 = -3.4e38f;
#pragma unroll
        for (int e = 0; e < NEXP; e++)
            if (e != i0 && acc[e] > v1) { v1 = acc[e]; i1 = e; }
        float e1 = expf(v1 - v0);
        float w0 = 1.f / (1.f + e1);
        float w1 = e1 * w0;
        float* c = g_combine + t * NEXP;
#pragma unroll
        for (int e = 0; e < NEXP; e++) c[e] = 0.f;
        c[i0] = w0;
        c[i1] = w1;
    }
}

// ---------------------------------------------------------------------------
// G1: H = x @ At^T, scaled by combine, tf32-written into g_xaug cols [1024,1152)
// Block 64x128, BK=32, 3-stage cp.async, 8 warps (2M x 4N), warp tile 32x32.
// ---------------------------------------------------------------------------
#define G1_AB 8192                      // 64*32*4
#define G1_STAGE 24576                  // (64+128)*32*4
#define G1_SMEM (3 * G1_STAGE)          // 73728
#define G1_KT 32

__global__ __launch_bounds__(256) void g1_kernel() {
    extern __shared__ char smem[];
    const uint32_t sb = smem_u32(smem);
    const int tid = threadIdx.x, lane = tid & 31, warp = tid >> 5;
    const int m0 = blockIdx.x * 64;
    const int wm = (warp & 1) * 32, wn = (warp >> 1) * 32;

    const float* ag[2]; uint32_t asw[2];
    const float* bg[4]; uint32_t bsw[4];
#pragma unroll
    for (int i = 0; i < 2; i++) {
        int idx = i * 256 + tid, r = idx >> 3, c = idx & 7;
        ag[i] = g_xaug + (size_t)(m0 + r) * KAUG + c * 4;
        asw[i] = r * 128 + ((c ^ (r & 7)) << 4);
    }
#pragma unroll
    for (int i = 0; i < 4; i++) {
        int idx = i * 256 + tid, r = idx >> 3, c = idx & 7;
        bg[i] = g_At + (size_t)r * DMODEL + c * 4;
        bsw[i] = r * 128 + ((c ^ (r & 7)) << 4);
    }

    const int lr = lane & 7, mi = lane >> 3;
    const uint32_t arow = wm + (mi & 1) * 8 + lr;
    const uint32_t abase = arow * 128, ax = arow & 7, ac = mi >> 1;
    const uint32_t brow = wn + (mi >> 1) * 8 + lr;
    const uint32_t bbase = brow * 128, bx = brow & 7, bc = mi & 1;

    float acc[2][4][4];
#pragma unroll
    for (int mt = 0; mt < 2; mt++)
#pragma unroll
        for (int nb = 0; nb < 4; nb++)
#pragma unroll
            for (int q = 0; q < 4; q++) acc[mt][nb][q] = 0.f;

    auto load_stage = [&](int s, int kt) {
        uint32_t base = sb + s * G1_STAGE;
#pragma unroll
        for (int i = 0; i < 2; i++) cp16(base + asw[i], ag[i] + kt * 32);
#pragma unroll
        for (int i = 0; i < 4; i++) cp16(base + G1_AB + bsw[i], bg[i] + kt * 32);
    };

    load_stage(0, 0); cp_commit();
    load_stage(1, 1); cp_commit();

    for (int kt = 0; kt < G1_KT; kt++) {
        cp_wait<1>();
        __syncthreads();
        int ld = kt + 2;
        if (ld < G1_KT) load_stage(ld % 3, ld);
        cp_commit();
        uint32_t stg = sb + (kt % 3) * G1_STAGE;
#pragma unroll
        for (int s = 0; s < 4; s++) {
            uint32_t a[2][4], b[2][4];
#pragma unroll
            for (int mt = 0; mt < 2; mt++)
                ldsm4(a[mt], stg + abase + mt * 2048 + (((2 * s + ac) ^ ax) << 4));
#pragma unroll
            for (int nt = 0; nt < 2; nt++)
                ldsm4(b[nt], stg + G1_AB + bbase + nt * 2048 + (((2 * s + bc) ^ bx) << 4));
#pragma unroll
            for (int mt = 0; mt < 2; mt++)
#pragma unroll
                for (int nb = 0; nb < 4; nb++)
                    mma_tf32(acc[mt][nb], a[mt], &b[nb >> 1][(nb & 1) * 2]);
        }
    }
    cp_wait<0>();

    const int grp = lane >> 2, th2 = (lane & 3) * 2;
#pragma unroll
    for (int mt = 0; mt < 2; mt++) {
        int r0 = m0 + wm + mt * 16 + grp;
#pragma unroll
        for (int nb = 0; nb < 4; nb++) {
            int col = wn + nb * 8 + th2;
            int e = col >> 4;
            float w0 = g_combine[r0 * NEXP + e];
            float w1 = g_combine[(r0 + 8) * NEXP + e];
            float2 o0 = make_float2(f2tf(acc[mt][nb][0] * w0), f2tf(acc[mt][nb][1] * w0));
            float2 o1 = make_float2(f2tf(acc[mt][nb][2] * w1), f2tf(acc[mt][nb][3] * w1));
            *(float2*)(g_xaug + (size_t)r0 * KAUG + DMODEL + col) = o0;
            *(float2*)(g_xaug + (size_t)(r0 + 8) * KAUG + DMODEL + col) = o1;
        }
    }
}

// ---------------------------------------------------------------------------
// G2: out = [x|hw] @ g_Bt^T + bias
// Block 128x128, BK=32, 3-stage cp.async, 8 warps (2M x 4N), warp tile 64x32.
// ---------------------------------------------------------------------------
#define G2_AB 16384                     // 128*32*4
#define G2_STAGE 32768                  // (128+128)*32*4
#define G2_SMEM (3 * G2_STAGE)          // 98304
#define G2_KT 36

__global__ __launch_bounds__(256) void g2_kernel(const float* __restrict__ bias,
                                                 float* __restrict__ out) {
    extern __shared__ char smem[];
    const uint32_t sb = smem_u32(smem);
    const int tid = threadIdx.x, lane = tid & 31, warp = tid >> 5;
    const int m0 = blockIdx.y * 128, n0 = blockIdx.x * 128;
    const int wm = (warp & 1) * 64, wn = (warp >> 1) * 32;

    const float* ag[4]; uint32_t asw[4];
    const float* bg[4]; uint32_t bsw[4];
#pragma unroll
    for (int i = 0; i < 4; i++) {
        int idx = i * 256 + tid, r = idx >> 3, c = idx & 7;
        ag[i] = g_xaug + (size_t)(m0 + r) * KAUG + c * 4;
        asw[i] = r * 128 + ((c ^ (r & 7)) << 4);
        bg[i] = g_Bt + (size_t)(n0 + r) * KAUG + c * 4;
        bsw[i] = asw[i];
    }

    const int lr = lane & 7, mi = lane >> 3;
    const uint32_t arow = wm + (mi & 1) * 8 + lr;
    const uint32_t abase = arow * 128, ax = arow & 7, ac = mi >> 1;
    const uint32_t brow = wn + (mi >> 1) * 8 + lr;
    const uint32_t bbase = brow * 128, bx = brow & 7, bc = mi & 1;

    float acc[4][4][4];
#pragma unroll
    for (int mt = 0; mt < 4; mt++)
#pragma unroll
        for (int nb = 0; nb < 4; nb++)
#pragma unroll
            for (int q = 0; q < 4; q++) acc[mt][nb][q] = 0.f;

    auto load_stage = [&](int s, int kt) {
        uint32_t base = sb + s * G2_STAGE;
#pragma unroll
        for (int i = 0; i < 4; i++) cp16(base + asw[i], ag[i] + kt * 32);
#pragma unroll
        for (int i = 0; i < 4; i++) cp16(base + G2_AB + bsw[i], bg[i] + kt * 32);
    };

    load_stage(0, 0); cp_commit();
    load_stage(1, 1); cp_commit();

    for (int kt = 0; kt < G2_KT; kt++) {
        cp_wait<1>();
        __syncthreads();
        int ld = kt + 2;
        if (ld < G2_KT) load_stage(ld % 3, ld);
        cp_commit();
        uint32_t stg = sb + (kt % 3) * G2_STAGE;
#pragma unroll
        for (int s = 0; s < 4; s++) {
            uint32_t a[4][4], b[2][4];
#pragma unroll
            for (int mt = 0; mt < 4; mt++)
                ldsm4(a[mt], stg + abase + mt * 2048 + (((2 * s + ac) ^ ax) << 4));
#pragma unroll
            for (int nt = 0; nt < 2; nt++)
                ldsm4(b[nt], stg + G2_AB + bbase + nt * 2048 + (((2 * s + bc) ^ bx) << 4));
#pragma unroll
            for (int mt = 0; mt < 4; mt++)
#pragma unroll
                for (int nb = 0; nb < 4; nb++)
                    mma_tf32(acc[mt][nb], a[mt], &b[nb >> 1][(nb & 1) * 2]);
        }
    }
    cp_wait<0>();

    const int grp = lane >> 2, th2 = (lane & 3) * 2;
#pragma unroll
    for (int mt = 0; mt < 4; mt++) {
        int r0 = m0 + wm + mt * 16 + grp;
#pragma unroll
        for (int nb = 0; nb < 4; nb++) {
            int col = n0 + wn + nb * 8 + th2;
            float2 bv = *(const float2*)(bias + col);
            float2 o0 = make_float2(acc[mt][nb][0] + bv.x, acc[mt][nb][1] + bv.y);
            float2 o1 = make_float2(acc[mt][nb][2] + bv.x, acc[mt][nb][3] + bv.y);
            *(float2*)(out + (size_t)r0 * DMODEL + col) = o0;
            *(float2*)(out + (size_t)(r0 + 8) * DMODEL + col) = o1;
        }
    }
}

// ---------------------------------------------------------------------------
extern "C" void kernel_launch(void* const* d_in, const int* in_sizes, int n_in,
                              void* d_out, int out_size) {
    const float* x  = (const float*)d_in[0];
    const float* Wg = (const float*)d_in[1];
    const float* A  = (const float*)d_in[2];
    const float* B  = (const float*)d_in[3];
    const float* Wb = (const float*)d_in[4];
    const float* bb = (const float*)d_in[5];
    float* out = (float*)d_out;

    static int attr_done = 0;
    if (!attr_done) {
        cudaFuncSetAttribute(g1_kernel, cudaFuncAttributeMaxDynamicSharedMemorySize, G1_SMEM);
        cudaFuncSetAttribute(g2_kernel, cudaFuncAttributeMaxDynamicSharedMemorySize, G2_SMEM);
        attr_done = 1;
    }

    build_bt_base<<<DMODEL, 256>>>(Wb);
    build_bt_lora<<<dim3(32, 4), dim3(32, 32)>>>(B);
    build_at<<<dim3(64, 8), dim3(16, 16)>>>(A);
    gating_cvt<<<N_TOK / 8, 256>>>(x, Wg);
    g1_kernel<<<N_TOK / 64, 256, G1_SMEM>>>();
    g2_kernel<<<dim3(DMODEL / 128, N_TOK / 128), 256, G2_SMEM>>>(bb, out);
}

// round 5
// speedup vs baseline: 3.9267x; 1.0374x over previous
#include <cuda_runtime.h>
#include <cstdint>

#define N_TOK 8192
#define DMODEL 1024
#define NEXP 8
#define RANK 16
#define HCOLS 128
#define KAUG 1152            // 1024 + 128

// ---------------------------------------------------------------------------
// Device scratch (no allocation allowed)
// ---------------------------------------------------------------------------
__device__ float g_combine[N_TOK * NEXP];                  // [N, 8]
__device__ float g_xaug[(size_t)N_TOK * KAUG];             // tf32 [x | hw], row-major [m][k]
__device__ float g_Bt[(size_t)DMODEL * KAUG];              // tf32 [n][k] = [Wb row | B^T row]
__device__ float g_At[HCOLS * DMODEL];                     // tf32 [n=e*16+r][k]

// ---------------------------------------------------------------------------
// Helpers
// ---------------------------------------------------------------------------
__device__ __forceinline__ float f2tf(float f) {
    unsigned u; asm("cvt.rna.tf32.f32 %0, %1;" : "=r"(u) : "f"(f));
    return __uint_as_float(u);
}
__device__ __forceinline__ uint32_t smem_u32(const void* p) {
    uint32_t a;
    asm("{ .reg .u64 t; cvta.to.shared.u64 t, %1; cvt.u32.u64 %0, t; }" : "=r"(a) : "l"(p));
    return a;
}
__device__ __forceinline__ void ldsm4(uint32_t* r, uint32_t addr) {
    asm volatile("ldmatrix.sync.aligned.m8n8.x4.shared.b16 {%0,%1,%2,%3}, [%4];"
                 : "=r"(r[0]), "=r"(r[1]), "=r"(r[2]), "=r"(r[3]) : "r"(addr));
}
__device__ __forceinline__ void cp16(uint32_t dst, const void* src) {
    asm volatile("cp.async.cg.shared.global [%0], [%1], 16;" :: "r"(dst), "l"(src));
}
__device__ __forceinline__ void cp_commit() {
    asm volatile("cp.async.commit_group;" ::: "memory");
}
template <int N> __device__ __forceinline__ void cp_wait() {
    asm volatile("cp.async.wait_group %0;" :: "n"(N) : "memory");
}
__device__ __forceinline__ void mma_tf32(float* c, const uint32_t* a, const uint32_t* b) {
    asm volatile(
        "mma.sync.aligned.m16n8k8.row.col.f32.tf32.tf32.f32 "
        "{%0,%1,%2,%3}, {%4,%5,%6,%7}, {%8,%9}, {%0,%1,%2,%3};"
        : "+f"(c[0]), "+f"(c[1]), "+f"(c[2]), "+f"(c[3])
        : "r"(a[0]), "r"(a[1]), "r"(a[2]), "r"(a[3]), "r"(b[0]), "r"(b[1]));
}

// ---------------------------------------------------------------------------
// Prep 1: g_Bt rows, cols [0,1024) = tf32(W_base[n][k])  (W_base is [N,K] k-major)
// ---------------------------------------------------------------------------
__global__ void build_bt_base(const float* __restrict__ Wb) {
    int n = blockIdx.x;
    int j = threadIdx.x * 4;
    float4 v = *(const float4*)(Wb + (size_t)n * DMODEL + j);
    float4 o = make_float4(f2tf(v.x), f2tf(v.y), f2tf(v.z), f2tf(v.w));
    *(float4*)(g_Bt + (size_t)n * KAUG + j) = o;
}

// Prep 2: g_Bt[n][1024+i] = tf32(B[i][n])  (B flattens to [128][1024])
__global__ void build_bt_lora(const float* __restrict__ B) {
    __shared__ float tile[32][33];
    int n0 = blockIdx.x * 32, i0 = blockIdx.y * 32;
    tile[threadIdx.y][threadIdx.x] =
        f2tf(B[(size_t)(i0 + threadIdx.y) * DMODEL + n0 + threadIdx.x]);
    __syncthreads();
    g_Bt[(size_t)(n0 + threadIdx.y) * KAUG + DMODEL + i0 + threadIdx.x] =
        tile[threadIdx.x][threadIdx.y];
}

// Prep 3: g_At[e*16+r][k] = tf32(A[e][k][r])
__global__ void build_at(const float* __restrict__ A) {
    __shared__ float tile[16][17];
    int e = blockIdx.y, k0 = blockIdx.x * 16;
    tile[threadIdx.x][threadIdx.y] =
        f2tf(A[(size_t)e * DMODEL * RANK + (size_t)(k0 + threadIdx.y) * RANK + threadIdx.x]);
    __syncthreads();
    g_At[(size_t)(e * RANK + threadIdx.y) * DMODEL + k0 + threadIdx.x] =
        tile[threadIdx.y][threadIdx.x];
}

// ---------------------------------------------------------------------------
// Gating + fused x->tf32 conversion into g_xaug[:, 0:1024].
// Wg staged in smem once per block (kills the per-warp L1 Wg re-reads).
// One warp per token, 8 warps/block.
// ---------------------------------------------------------------------------
__global__ __launch_bounds__(256) void gating_cvt(const float* __restrict__ x,
                                                  const float* __restrict__ Wg) {
    __shared__ float wgs[NEXP * DMODEL];   // 32 KB
#pragma unroll
    for (int i = 0; i < NEXP * DMODEL / 4 / 256; i++)
        ((float4*)wgs)[i * 256 + threadIdx.x] = ((const float4*)Wg)[i * 256 + threadIdx.x];
    __syncthreads();

    int warp = threadIdx.x >> 5, lane = threadIdx.x & 31;
    int t = blockIdx.x * 8 + warp;
    const float* xr = x + (size_t)t * DMODEL;
    float* xo = g_xaug + (size_t)t * KAUG;
    float acc[NEXP];
#pragma unroll
    for (int e = 0; e < NEXP; e++) acc[e] = 0.f;
#pragma unroll
    for (int kk = 0; kk < 8; kk++) {
        int col = kk * 128 + lane * 4;
        float4 v = *(const float4*)(xr + col);
        float4 cv = make_float4(f2tf(v.x), f2tf(v.y), f2tf(v.z), f2tf(v.w));
        *(float4*)(xo + col) = cv;
#pragma unroll
        for (int e = 0; e < NEXP; e++) {
            float4 w = *(const float4*)(wgs + e * DMODEL + col);
            acc[e] += v.x * w.x + v.y * w.y + v.z * w.z + v.w * w.w;
        }
    }
#pragma unroll
    for (int e = 0; e < NEXP; e++) {
#pragma unroll
        for (int o = 16; o > 0; o >>= 1)
            acc[e] += __shfl_xor_sync(0xffffffffu, acc[e], o);
    }
    if (lane == 0) {
        int i0 = 0; float v0 = acc[0];
#pragma unroll
        for (int e = 1; e < NEXP; e++)
            if (acc[e] > v0) { v0 = acc[e]; i0 = e; }
        int i1 = -1; float v1 = -3.4e38f;
#pragma unroll
        for (int e = 0; e < NEXP; e++)
            if (e != i0 && acc[e] > v1) { v1 = acc[e]; i1 = e; }
        float e1 = expf(v1 - v0);
        float w0 = 1.f / (1.f + e1);
        float w1 = e1 * w0;
        float* c = g_combine + t * NEXP;
#pragma unroll
        for (int e = 0; e < NEXP; e++) c[e] = 0.f;
        c[i0] = w0;
        c[i1] = w1;
    }
}

// ---------------------------------------------------------------------------
// G1: H = x @ At^T, scaled by combine, tf32-written into g_xaug cols [1024,1152)
// Block 64x128, BK=32, 3-stage cp.async, 8 warps (2M x 4N), warp tile 32x32.
// 2 CTAs/SM.
// ---------------------------------------------------------------------------
#define G1_AB 8192                      // 64*32*4
#define G1_STAGE 24576                  // (64+128)*32*4
#define G1_SMEM (3 * G1_STAGE)          // 73728
#define G1_KT 32

__global__ __launch_bounds__(256, 2) void g1_kernel() {
    extern __shared__ char smem[];
    const uint32_t sb = smem_u32(smem);
    const int tid = threadIdx.x, lane = tid & 31, warp = tid >> 5;
    const int m0 = blockIdx.x * 64;
    const int wm = (warp & 1) * 32, wn = (warp >> 1) * 32;

    const float* ag[2]; uint32_t asw[2];
    const float* bg[4]; uint32_t bsw[4];
#pragma unroll
    for (int i = 0; i < 2; i++) {
        int idx = i * 256 + tid, r = idx >> 3, c = idx & 7;
        ag[i] = g_xaug + (size_t)(m0 + r) * KAUG + c * 4;
        asw[i] = r * 128 + ((c ^ (r & 7)) << 4);
    }
#pragma unroll
    for (int i = 0; i < 4; i++) {
        int idx = i * 256 + tid, r = idx >> 3, c = idx & 7;
        bg[i] = g_At + (size_t)r * DMODEL + c * 4;
        bsw[i] = r * 128 + ((c ^ (r & 7)) << 4);
    }

    const int lr = lane & 7, mi = lane >> 3;
    const uint32_t arow = wm + (mi & 1) * 8 + lr;
    const uint32_t abase = arow * 128, ax = arow & 7, ac = mi >> 1;
    const uint32_t brow = wn + (mi >> 1) * 8 + lr;
    const uint32_t bbase = brow * 128, bx = brow & 7, bc = mi & 1;

    float acc[2][4][4];
#pragma unroll
    for (int mt = 0; mt < 2; mt++)
#pragma unroll
        for (int nb = 0; nb < 4; nb++)
#pragma unroll
            for (int q = 0; q < 4; q++) acc[mt][nb][q] = 0.f;

    auto load_stage = [&](int s, int kt) {
        uint32_t base = sb + s * G1_STAGE;
#pragma unroll
        for (int i = 0; i < 2; i++) cp16(base + asw[i], ag[i] + kt * 32);
#pragma unroll
        for (int i = 0; i < 4; i++) cp16(base + G1_AB + bsw[i], bg[i] + kt * 32);
    };

    load_stage(0, 0); cp_commit();
    load_stage(1, 1); cp_commit();

    for (int kt = 0; kt < G1_KT; kt++) {
        cp_wait<1>();
        __syncthreads();
        int ld = kt + 2;
        if (ld < G1_KT) load_stage(ld % 3, ld);
        cp_commit();
        uint32_t stg = sb + (kt % 3) * G1_STAGE;
#pragma unroll
        for (int s = 0; s < 4; s++) {
            uint32_t a[2][4], b[2][4];
#pragma unroll
            for (int mt = 0; mt < 2; mt++)
                ldsm4(a[mt], stg + abase + mt * 2048 + (((2 * s + ac) ^ ax) << 4));
#pragma unroll
            for (int nt = 0; nt < 2; nt++)
                ldsm4(b[nt], stg + G1_AB + bbase + nt * 2048 + (((2 * s + bc) ^ bx) << 4));
#pragma unroll
            for (int mt = 0; mt < 2; mt++)
#pragma unroll
                for (int nb = 0; nb < 4; nb++)
                    mma_tf32(acc[mt][nb], a[mt], &b[nb >> 1][(nb & 1) * 2]);
        }
    }
    cp_wait<0>();

    const int grp = lane >> 2, th2 = (lane & 3) * 2;
#pragma unroll
    for (int mt = 0; mt < 2; mt++) {
        int r0 = m0 + wm + mt * 16 + grp;
#pragma unroll
        for (int nb = 0; nb < 4; nb++) {
            int col = wn + nb * 8 + th2;
            int e = col >> 4;
            float w0 = g_combine[r0 * NEXP + e];
            float w1 = g_combine[(r0 + 8) * NEXP + e];
            float2 o0 = make_float2(f2tf(acc[mt][nb][0] * w0), f2tf(acc[mt][nb][1] * w0));
            float2 o1 = make_float2(f2tf(acc[mt][nb][2] * w1), f2tf(acc[mt][nb][3] * w1));
            *(float2*)(g_xaug + (size_t)r0 * KAUG + DMODEL + col) = o0;
            *(float2*)(g_xaug + (size_t)(r0 + 8) * KAUG + DMODEL + col) = o1;
        }
    }
}

// ---------------------------------------------------------------------------
// G2: out = [x|hw] @ g_Bt^T + bias
// Block 128x128, BK=32, 3-stage cp.async, 8 warps (2M x 4N), warp tile 64x32.
// 2 CTAs/SM (2 x 96KB smem).
// ---------------------------------------------------------------------------
#define G2_AB 16384                     // 128*32*4
#define G2_STAGE 32768                  // (128+128)*32*4
#define G2_SMEM (3 * G2_STAGE)          // 98304
#define G2_KT 36

__global__ __launch_bounds__(256, 2) void g2_kernel(const float* __restrict__ bias,
                                                    float* __restrict__ out) {
    extern __shared__ char smem[];
    const uint32_t sb = smem_u32(smem);
    const int tid = threadIdx.x, lane = tid & 31, warp = tid >> 5;
    const int m0 = blockIdx.y * 128, n0 = blockIdx.x * 128;
    const int wm = (warp & 1) * 64, wn = (warp >> 1) * 32;

    const float* ag[4]; uint32_t asw[4];
    const float* bg[4]; uint32_t bsw[4];
#pragma unroll
    for (int i = 0; i < 4; i++) {
        int idx = i * 256 + tid, r = idx >> 3, c = idx & 7;
        ag[i] = g_xaug + (size_t)(m0 + r) * KAUG + c * 4;
        asw[i] = r * 128 + ((c ^ (r & 7)) << 4);
        bg[i] = g_Bt + (size_t)(n0 + r) * KAUG + c * 4;
        bsw[i] = asw[i];
    }

    const int lr = lane & 7, mi = lane >> 3;
    const uint32_t arow = wm + (mi & 1) * 8 + lr;
    const uint32_t abase = arow * 128, ax = arow & 7, ac = mi >> 1;
    const uint32_t brow = wn + (mi >> 1) * 8 + lr;
    const uint32_t bbase = brow * 128, bx = brow & 7, bc = mi & 1;

    float acc[4][4][4];
#pragma unroll
    for (int mt = 0; mt < 4; mt++)
#pragma unroll
        for (int nb = 0; nb < 4; nb++)
#pragma unroll
            for (int q = 0; q < 4; q++) acc[mt][nb][q] = 0.f;

    auto load_stage = [&](int s, int kt) {
        uint32_t base = sb + s * G2_STAGE;
#pragma unroll
        for (int i = 0; i < 4; i++) cp16(base + asw[i], ag[i] + kt * 32);
#pragma unroll
        for (int i = 0; i < 4; i++) cp16(base + G2_AB + bsw[i], bg[i] + kt * 32);
    };

    load_stage(0, 0); cp_commit();
    load_stage(1, 1); cp_commit();

    for (int kt = 0; kt < G2_KT; kt++) {
        cp_wait<1>();
        __syncthreads();
        int ld = kt + 2;
        if (ld < G2_KT) load_stage(ld % 3, ld);
        cp_commit();
        uint32_t stg = sb + (kt % 3) * G2_STAGE;
#pragma unroll
        for (int s = 0; s < 4; s++) {
            uint32_t a[4][4], b[2][4];
#pragma unroll
            for (int mt = 0; mt < 4; mt++)
                ldsm4(a[mt], stg + abase + mt * 2048 + (((2 * s + ac) ^ ax) << 4));
#pragma unroll
            for (int nt = 0; nt < 2; nt++)
                ldsm4(b[nt], stg + G2_AB + bbase + nt * 2048 + (((2 * s + bc) ^ bx) << 4));
#pragma unroll
            for (int mt = 0; mt < 4; mt++)
#pragma unroll
                for (int nb = 0; nb < 4; nb++)
                    mma_tf32(acc[mt][nb], a[mt], &b[nb >> 1][(nb & 1) * 2]);
        }
    }
    cp_wait<0>();

    const int grp = lane >> 2, th2 = (lane & 3) * 2;
#pragma unroll
    for (int mt = 0; mt < 4; mt++) {
        int r0 = m0 + wm + mt * 16 + grp;
#pragma unroll
        for (int nb = 0; nb < 4; nb++) {
            int col = n0 + wn + nb * 8 + th2;
            float2 bv = *(const float2*)(bias + col);
            float2 o0 = make_float2(acc[mt][nb][0] + bv.x, acc[mt][nb][1] + bv.y);
            float2 o1 = make_float2(acc[mt][nb][2] + bv.x, acc[mt][nb][3] + bv.y);
            *(float2*)(out + (size_t)r0 * DMODEL + col) = o0;
            *(float2*)(out + (size_t)(r0 + 8) * DMODEL + col) = o1;
        }
    }
}

// ---------------------------------------------------------------------------
extern "C" void kernel_launch(void* const* d_in, const int* in_sizes, int n_in,
                              void* d_out, int out_size) {
    const float* x  = (const float*)d_in[0];
    const float* Wg = (const float*)d_in[1];
    const float* A  = (const float*)d_in[2];
    const float* B  = (const float*)d_in[3];
    const float* Wb = (const float*)d_in[4];
    const float* bb = (const float*)d_in[5];
    float* out = (float*)d_out;

    static int attr_done = 0;
    if (!attr_done) {
        cudaFuncSetAttribute(g1_kernel, cudaFuncAttributeMaxDynamicSharedMemorySize, G1_SMEM);
        cudaFuncSetAttribute(g2_kernel, cudaFuncAttributeMaxDynamicSharedMemorySize, G2_SMEM);
        attr_done = 1;
    }

    build_bt_base<<<DMODEL, 256>>>(Wb);
    build_bt_lora<<<dim3(32, 4), dim3(32, 32)>>>(B);
    build_at<<<dim3(64, 8), dim3(16, 16)>>>(A);
    gating_cvt<<<N_TOK / 8, 256>>>(x, Wg);
    g1_kernel<<<N_TOK / 64, 256, G1_SMEM>>>();
    g2_kernel<<<dim3(DMODEL / 128, N_TOK / 128), 256, G2_SMEM>>>(bb, out);
}